// round 2
// baseline (speedup 1.0000x reference)
#include <cuda_runtime.h>

#define HDIM 128
#define MAXN 50000
#define MAXE 600000
#define MAXG 128
#define CDIM 10

// ---------------- scratch (no allocations allowed) ----------------
__device__ int   g_is64;
__device__ int   g_cnt[MAXN];
__device__ float g_dinv[MAXN];
__device__ int   g_ptr[MAXN + 1];
__device__ int   g_pos[MAXN];
__device__ int   g_csrc[MAXE];
__device__ int   g_bsum[128];
__device__ float g_h[(size_t)MAXN * HDIM];
__device__ float g_tmp[(size_t)MAXN * HDIM];
__device__ float g_pool[MAXG * HDIM];
__device__ float g_gcnt[MAXG];

__device__ __forceinline__ int loadIdx(const void* p, long long i, int is64) {
    if (is64) return (int)((const long long*)p)[i];
    return ((const int*)p)[i];
}

// Detect whether index buffers are int64 or int32. Values are < 50000, so if
// the data is int64 every odd 32-bit word is 0. For int32 data odd words are
// random node ids; 32 of them all being zero is ~(1/50000)^32.
__global__ void k_detect(const void* ei) {
    if (threadIdx.x == 0) {
        const int* w = (const int*)ei;
        int all0 = 1;
        for (int i = 0; i < 32; i++) if (w[2 * i + 1] != 0) all0 = 0;
        g_is64 = all0;
    }
}

__global__ void k_zero_cnt(int n) {
    int i = blockIdx.x * blockDim.x + threadIdx.x;
    if (i < n) g_cnt[i] = 0;
}

__global__ void k_deg(const void* ei, int E) {
    int e = blockIdx.x * blockDim.x + threadIdx.x;
    if (e >= E) return;
    int is64 = g_is64;
    int d = loadIdx(ei, (long long)E + e, is64);
    atomicAdd(&g_cnt[d], 1);
}

__global__ void k_dinv(int n) {
    int i = blockIdx.x * blockDim.x + threadIdx.x;
    if (i < n) g_dinv[i] = rsqrtf((float)(g_cnt[i] + 1));  // +1 = self-loop
}

// ---------------- exclusive scan of g_cnt -> g_ptr ----------------
__global__ void k_scan1(int n) {
    __shared__ int s[1024];
    int tid = threadIdx.x;
    int i = blockIdx.x * 1024 + tid;
    int v = (i < n) ? g_cnt[i] : 0;
    s[tid] = v;
    __syncthreads();
    for (int off = 1; off < 1024; off <<= 1) {
        int t = (tid >= off) ? s[tid - off] : 0;
        __syncthreads();
        s[tid] += t;
        __syncthreads();
    }
    if (i < n) g_ptr[i] = s[tid] - v;   // exclusive within block
    if (tid == 1023) g_bsum[blockIdx.x] = s[tid];
}

__global__ void k_scan2(int nb, int n) {
    if (threadIdx.x == 0) {
        int acc = 0;
        for (int b = 0; b < nb; b++) { int t = g_bsum[b]; g_bsum[b] = acc; acc += t; }
        g_ptr[n] = acc;
    }
}

__global__ void k_scan3(int n) {
    int i = blockIdx.x * 1024 + threadIdx.x;
    if (i < n) {
        int p = g_ptr[i] + g_bsum[blockIdx.x];
        g_ptr[i] = p;
        g_pos[i] = p;
    }
}

__global__ void k_fill(const void* ei, int E) {
    int e = blockIdx.x * blockDim.x + threadIdx.x;
    if (e >= E) return;
    int is64 = g_is64;
    int s = loadIdx(ei, e, is64);
    int d = loadIdx(ei, (long long)E + e, is64);
    int p = atomicAdd(&g_pos[d], 1);
    g_csrc[p] = s;
}

// ---------------- GEMM: g_tmp = A @ W  (A = Aext or g_h), 128x128 W ----------------
__global__ __launch_bounds__(256) void k_gemm(const float* __restrict__ Aext,
                                              const float* __restrict__ W,
                                              int nrows) {
    __shared__ float sW[HDIM * HDIM];   // 64KB, whole weight matrix
    __shared__ float sh[8][HDIM];       // 8 input rows
    const float* A = Aext ? Aext : g_h;
    int tid = threadIdx.x;
    float4* sW4 = (float4*)sW;
    const float4* W4 = (const float4*)W;
#pragma unroll
    for (int j = 0; j < 16; j++) sW4[tid + j * 256] = W4[tid + j * 256];
    __syncthreads();

    int warp = tid >> 5, lane = tid & 31;
    int rowbase = blockIdx.x * 128;
    const float4* A4 = (const float4*)A;
    float4* O4 = (float4*)g_tmp;

    for (int gI = 0; gI < 16; gI++) {
        int lrow = rowbase + gI * 8 + (tid >> 5);
        if (lrow < nrows) ((float4*)sh)[tid] = A4[(size_t)lrow * 32 + lane];
        __syncthreads();
        int row = rowbase + gI * 8 + warp;
        if (row < nrows) {
            float4 acc = make_float4(0.f, 0.f, 0.f, 0.f);
#pragma unroll
            for (int k = 0; k < HDIM; k++) {
                float a = sh[warp][k];           // broadcast, conflict-free
                float4 w = sW4[k * 32 + lane];   // 4-phase, conflict-free
                acc.x += a * w.x; acc.y += a * w.y;
                acc.z += a * w.z; acc.w += a * w.w;
            }
            O4[(size_t)row * 32 + lane] = acc;
        }
        __syncthreads();
    }
}

// ---------------- aggregation: g_h = relu(D^-1/2 A D^-1/2 * g_tmp + b) ----------------
__global__ __launch_bounds__(256) void k_agg(const float* __restrict__ bias, int n) {
    int warp = threadIdx.x >> 5, lane = threadIdx.x & 31;
    int node = blockIdx.x * 8 + warp;
    if (node >= n) return;
    const float4* t4 = (const float4*)g_tmp;
    float4 acc = make_float4(0.f, 0.f, 0.f, 0.f);
    int beg = g_ptr[node], end = g_ptr[node + 1];
    for (int p = beg; p < end; p++) {
        int s = g_csrc[p];
        float ds = g_dinv[s];
        float4 v = t4[(size_t)s * 32 + lane];
        acc.x += ds * v.x; acc.y += ds * v.y;
        acc.z += ds * v.z; acc.w += ds * v.w;
    }
    float di = g_dinv[node];
    float di2 = di * di;
    float4 sv = t4[(size_t)node * 32 + lane];
    float4 b = ((const float4*)bias)[lane];
    float4 r;
    r.x = fmaxf(di * acc.x + di2 * sv.x + b.x, 0.f);
    r.y = fmaxf(di * acc.y + di2 * sv.y + b.y, 0.f);
    r.z = fmaxf(di * acc.z + di2 * sv.z + b.z, 0.f);
    r.w = fmaxf(di * acc.w + di2 * sv.w + b.w, 0.f);
    ((float4*)g_h)[(size_t)node * 32 + lane] = r;
}

// ---------------- pooling ----------------
__global__ void k_zero_pool(int g) {
    int i = blockIdx.x * blockDim.x + threadIdx.x;
    if (i < g * HDIM) g_pool[i] = 0.f;
    if (i < g) g_gcnt[i] = 0.f;
}

__global__ void k_gcount(const void* batch, int n) {
    int i = blockIdx.x * blockDim.x + threadIdx.x;
    if (i >= n) return;
    int g = loadIdx(batch, i, g_is64);
    atomicAdd(&g_gcnt[g], 1.0f);
}

// batch is sorted: run-length accumulate per block, flush on graph change.
__global__ __launch_bounds__(128) void k_pool(const void* batch, int n) {
    int f = threadIdx.x;
    int n0 = blockIdx.x * 256;
    int n1 = min(n0 + 256, n);
    if (n0 >= n) return;
    int is64 = g_is64;
    int curg = loadIdx(batch, n0, is64);
    float acc = 0.f;
    for (int i = n0; i < n1; i++) {
        int g = loadIdx(batch, i, is64);
        if (g != curg) {
            atomicAdd(&g_pool[curg * HDIM + f], acc);
            acc = 0.f; curg = g;
        }
        acc += g_h[(size_t)i * HDIM + f];
    }
    atomicAdd(&g_pool[curg * HDIM + f], acc);
}

// ---------------- classifier: out = (pool/cnt) @ Wl + bl ----------------
__global__ void k_cls(const float* __restrict__ Wl, const float* __restrict__ bl,
                      float* __restrict__ out) {
    int g = blockIdx.x;
    int lane = threadIdx.x;
    float invc = 1.0f / fmaxf(g_gcnt[g], 1.0f);
    float acc = (lane < CDIM) ? bl[lane] : 0.f;
    for (int k = 0; k < HDIM; k++) {
        float p = g_pool[g * HDIM + k] * invc;
        if (lane < CDIM) acc += p * Wl[k * CDIM + lane];
    }
    if (lane < CDIM) out[g * CDIM + lane] = acc;
}

// ---------------- launch ----------------
extern "C" void kernel_launch(void* const* d_in, const int* in_sizes, int n_in,
                              void* d_out, int out_size) {
    const float* x  = (const float*)d_in[0];
    const float* W1 = (const float*)d_in[1];
    const float* b1 = (const float*)d_in[2];
    const float* W2 = (const float*)d_in[3];
    const float* b2 = (const float*)d_in[4];
    const float* W3 = (const float*)d_in[5];
    const float* b3 = (const float*)d_in[6];
    const float* Wl = (const float*)d_in[7];
    const float* bl = (const float*)d_in[8];
    const void*  ei = d_in[9];
    const void*  bt = d_in[10];

    int N = in_sizes[0] / HDIM;
    int E = in_sizes[9] / 2;
    int G = out_size / CDIM;

    k_detect<<<1, 32>>>(ei);
    k_zero_cnt<<<(N + 255) / 256, 256>>>(N);
    k_deg<<<(E + 255) / 256, 256>>>(ei, E);
    k_dinv<<<(N + 255) / 256, 256>>>(N);

    int nb = (N + 1023) / 1024;
    k_scan1<<<nb, 1024>>>(N);
    k_scan2<<<1, 32>>>(nb, N);
    k_scan3<<<nb, 1024>>>(N);
    k_fill<<<(E + 255) / 256, 256>>>(ei, E);

    int gemm_blocks = (N + 127) / 128;
    int agg_blocks  = (N + 7) / 8;

    k_gemm<<<gemm_blocks, 256>>>(x, W1, N);
    k_agg<<<agg_blocks, 256>>>(b1, N);
    k_gemm<<<gemm_blocks, 256>>>(nullptr, W2, N);
    k_agg<<<agg_blocks, 256>>>(b2, N);
    k_gemm<<<gemm_blocks, 256>>>(nullptr, W3, N);
    k_agg<<<agg_blocks, 256>>>(b3, N);

    k_zero_pool<<<(G * HDIM + 255) / 256, 256>>>(G);
    k_gcount<<<(N + 255) / 256, 256>>>(bt, N);
    k_pool<<<(N + 255) / 256, 128>>>(bt, N);
    k_cls<<<G, 32>>>(Wl, bl, (float*)d_out);
}

// round 3
// speedup vs baseline: 1.6009x; 1.6009x over previous
#include <cuda_runtime.h>

#define HDIM 128
#define MAXN 50000
#define MAXE 600000
#define MAXG 128
#define CDIM 10
#define BM 128
#define BK 16

// ---------------- scratch (no allocations allowed) ----------------
__device__ int   g_is64;
__device__ int   g_cnt[MAXN];
__device__ float g_dinv[MAXN];
__device__ int   g_ptr[MAXN + 1];
__device__ int   g_pos[MAXN];
__device__ int   g_csrc[MAXE];
__device__ int   g_bsum[128];
__device__ float g_h[(size_t)MAXN * HDIM];
__device__ float g_tmp[(size_t)MAXN * HDIM];
__device__ float g_pool[MAXG * HDIM];
__device__ float g_gcnt[MAXG];

__device__ __forceinline__ int loadIdx(const void* p, long long i, int is64) {
    if (is64) return (int)((const long long*)p)[i];
    return ((const int*)p)[i];
}

// int64 vs int32 index autodetect (node ids < 50000 -> odd words all zero for int64)
__global__ void k_detect(const void* ei) {
    if (threadIdx.x == 0) {
        const int* w = (const int*)ei;
        int all0 = 1;
        for (int i = 0; i < 32; i++) if (w[2 * i + 1] != 0) all0 = 0;
        g_is64 = all0;
    }
}

__global__ void k_zero_cnt(int n) {
    int i = blockIdx.x * blockDim.x + threadIdx.x;
    if (i < n) g_cnt[i] = 0;
}

__global__ void k_deg(const void* ei, int E) {
    int e = blockIdx.x * blockDim.x + threadIdx.x;
    if (e >= E) return;
    int d = loadIdx(ei, (long long)E + e, g_is64);
    atomicAdd(&g_cnt[d], 1);
}

__global__ void k_dinv(int n) {
    int i = blockIdx.x * blockDim.x + threadIdx.x;
    if (i < n) g_dinv[i] = rsqrtf((float)(g_cnt[i] + 1));  // +1 = self-loop
}

// ---------------- exclusive scan of g_cnt -> g_ptr ----------------
__global__ void k_scan1(int n) {
    __shared__ int s[1024];
    int tid = threadIdx.x;
    int i = blockIdx.x * 1024 + tid;
    int v = (i < n) ? g_cnt[i] : 0;
    s[tid] = v;
    __syncthreads();
    for (int off = 1; off < 1024; off <<= 1) {
        int t = (tid >= off) ? s[tid - off] : 0;
        __syncthreads();
        s[tid] += t;
        __syncthreads();
    }
    if (i < n) g_ptr[i] = s[tid] - v;
    if (tid == 1023) g_bsum[blockIdx.x] = s[tid];
}

__global__ void k_scan2(int nb, int n) {
    if (threadIdx.x == 0) {
        int acc = 0;
        for (int b = 0; b < nb; b++) { int t = g_bsum[b]; g_bsum[b] = acc; acc += t; }
        g_ptr[n] = acc;
    }
}

__global__ void k_scan3(int n) {
    int i = blockIdx.x * 1024 + threadIdx.x;
    if (i < n) {
        int p = g_ptr[i] + g_bsum[blockIdx.x];
        g_ptr[i] = p;
        g_pos[i] = p;
    }
}

__global__ void k_fill(const void* ei, int E) {
    int e = blockIdx.x * blockDim.x + threadIdx.x;
    if (e >= E) return;
    int is64 = g_is64;
    int s = loadIdx(ei, e, is64);
    int d = loadIdx(ei, (long long)E + e, is64);
    int p = atomicAdd(&g_pos[d], 1);
    g_csrc[p] = s;
}

// ---------------- GEMM: g_tmp = A @ W, register-tiled 8x8 per thread ----------------
__global__ __launch_bounds__(256, 2) void k_gemm(const float* __restrict__ Aext,
                                                 const float* __restrict__ W,
                                                 int nrows) {
    __shared__ float sA[2][BK][BM];     // A tile transposed: sA[k][row]
    __shared__ float sW[2][BK][HDIM];   // W tile: sW[k][col]
    const float* A = Aext ? Aext : g_h;

    int tid = threadIdx.x;
    int tx = tid & 15;                  // output col group (tx*8 .. +8)
    int ty = tid >> 4;                  // output row group (ty*8 .. +8)
    int rowbase = blockIdx.x * BM;

    // A-load mapping: 2 passes; row = tid>>2 (+64), float4 k-group = tid&3
    int arow = tid >> 2;
    int akg  = tid & 3;
    // W-load mapping: 2 passes; k = tid>>5 (+8), float4 col-group = tid&31
    int wk = tid >> 5;
    int wc = tid & 31;

    float4 aref[2], wref[2];

    // prologue: global -> regs -> smem buf 0
    {
#pragma unroll
        for (int p = 0; p < 2; p++) {
            int r = min(rowbase + arow + p * 64, nrows - 1);
            aref[p] = *(const float4*)&A[(size_t)r * HDIM + akg * 4];
            wref[p] = *(const float4*)&W[(size_t)(wk + p * 8) * HDIM + wc * 4];
        }
#pragma unroll
        for (int p = 0; p < 2; p++) {
            sA[0][akg * 4 + 0][arow + p * 64] = aref[p].x;
            sA[0][akg * 4 + 1][arow + p * 64] = aref[p].y;
            sA[0][akg * 4 + 2][arow + p * 64] = aref[p].z;
            sA[0][akg * 4 + 3][arow + p * 64] = aref[p].w;
            *(float4*)&sW[0][wk + p * 8][wc * 4] = wref[p];
        }
        __syncthreads();
    }

    float acc[8][8];
#pragma unroll
    for (int i = 0; i < 8; i++)
#pragma unroll
        for (int j = 0; j < 8; j++) acc[i][j] = 0.f;

    const int NT = HDIM / BK;  // 8 k-tiles
#pragma unroll 1
    for (int kt = 0; kt < NT; kt++) {
        int buf = kt & 1;
        if (kt + 1 < NT) {
#pragma unroll
            for (int p = 0; p < 2; p++) {
                int r = min(rowbase + arow + p * 64, nrows - 1);
                aref[p] = *(const float4*)&A[(size_t)r * HDIM + (kt + 1) * BK + akg * 4];
                wref[p] = *(const float4*)&W[(size_t)((kt + 1) * BK + wk + p * 8) * HDIM + wc * 4];
            }
        }

#pragma unroll
        for (int kk = 0; kk < BK; kk++) {
            float4 a0 = *(const float4*)&sA[buf][kk][ty * 8];
            float4 a1 = *(const float4*)&sA[buf][kk][ty * 8 + 4];
            float4 b0 = *(const float4*)&sW[buf][kk][tx * 8];
            float4 b1 = *(const float4*)&sW[buf][kk][tx * 8 + 4];
            float av[8] = {a0.x, a0.y, a0.z, a0.w, a1.x, a1.y, a1.z, a1.w};
            float bv[8] = {b0.x, b0.y, b0.z, b0.w, b1.x, b1.y, b1.z, b1.w};
#pragma unroll
            for (int i = 0; i < 8; i++)
#pragma unroll
                for (int j = 0; j < 8; j++) acc[i][j] += av[i] * bv[j];
        }

        if (kt + 1 < NT) {
            int nb = buf ^ 1;
#pragma unroll
            for (int p = 0; p < 2; p++) {
                sA[nb][akg * 4 + 0][arow + p * 64] = aref[p].x;
                sA[nb][akg * 4 + 1][arow + p * 64] = aref[p].y;
                sA[nb][akg * 4 + 2][arow + p * 64] = aref[p].z;
                sA[nb][akg * 4 + 3][arow + p * 64] = aref[p].w;
                *(float4*)&sW[nb][wk + p * 8][wc * 4] = wref[p];
            }
            __syncthreads();
        }
    }

    // epilogue
#pragma unroll
    for (int i = 0; i < 8; i++) {
        int r = rowbase + ty * 8 + i;
        if (r < nrows) {
            float4 o0 = make_float4(acc[i][0], acc[i][1], acc[i][2], acc[i][3]);
            float4 o1 = make_float4(acc[i][4], acc[i][5], acc[i][6], acc[i][7]);
            *(float4*)&g_tmp[(size_t)r * HDIM + tx * 8] = o0;
            *(float4*)&g_tmp[(size_t)r * HDIM + tx * 8 + 4] = o1;
        }
    }
}

// ---------------- aggregation: g_h = relu(D^-1/2 A D^-1/2 * g_tmp + b) ----------------
__global__ __launch_bounds__(256) void k_agg(const float* __restrict__ bias, int n) {
    int warp = threadIdx.x >> 5, lane = threadIdx.x & 31;
    int node = blockIdx.x * 8 + warp;
    if (node >= n) return;
    const float4* t4 = (const float4*)g_tmp;
    float4 acc = make_float4(0.f, 0.f, 0.f, 0.f);
    int beg = g_ptr[node], end = g_ptr[node + 1];
#pragma unroll 4
    for (int p = beg; p < end; p++) {
        int s = g_csrc[p];
        float ds = g_dinv[s];
        float4 v = t4[(size_t)s * 32 + lane];
        acc.x += ds * v.x; acc.y += ds * v.y;
        acc.z += ds * v.z; acc.w += ds * v.w;
    }
    float di = g_dinv[node];
    float di2 = di * di;
    float4 sv = t4[(size_t)node * 32 + lane];
    float4 b = ((const float4*)bias)[lane];
    float4 r;
    r.x = fmaxf(di * acc.x + di2 * sv.x + b.x, 0.f);
    r.y = fmaxf(di * acc.y + di2 * sv.y + b.y, 0.f);
    r.z = fmaxf(di * acc.z + di2 * sv.z + b.z, 0.f);
    r.w = fmaxf(di * acc.w + di2 * sv.w + b.w, 0.f);
    ((float4*)g_h)[(size_t)node * 32 + lane] = r;
}

// ---------------- pooling ----------------
__global__ void k_zero_pool(int g) {
    int i = blockIdx.x * blockDim.x + threadIdx.x;
    if (i < g * HDIM) g_pool[i] = 0.f;
    if (i < g) g_gcnt[i] = 0.f;
}

__global__ void k_gcount(const void* batch, int n) {
    int i = blockIdx.x * blockDim.x + threadIdx.x;
    if (i >= n) return;
    int g = loadIdx(batch, i, g_is64);
    atomicAdd(&g_gcnt[g], 1.0f);
}

__global__ __launch_bounds__(128) void k_pool(const void* batch, int n) {
    int f = threadIdx.x;
    int n0 = blockIdx.x * 256;
    int n1 = min(n0 + 256, n);
    if (n0 >= n) return;
    int is64 = g_is64;
    int curg = loadIdx(batch, n0, is64);
    float acc = 0.f;
    for (int i = n0; i < n1; i++) {
        int g = loadIdx(batch, i, is64);
        if (g != curg) {
            atomicAdd(&g_pool[curg * HDIM + f], acc);
            acc = 0.f; curg = g;
        }
        acc += g_h[(size_t)i * HDIM + f];
    }
    atomicAdd(&g_pool[curg * HDIM + f], acc);
}

// ---------------- classifier ----------------
__global__ void k_cls(const float* __restrict__ Wl, const float* __restrict__ bl,
                      float* __restrict__ out) {
    int g = blockIdx.x;
    int lane = threadIdx.x;
    float invc = 1.0f / fmaxf(g_gcnt[g], 1.0f);
    float acc = (lane < CDIM) ? bl[lane] : 0.f;
    for (int k = 0; k < HDIM; k++) {
        float p = g_pool[g * HDIM + k] * invc;
        if (lane < CDIM) acc += p * Wl[k * CDIM + lane];
    }
    if (lane < CDIM) out[g * CDIM + lane] = acc;
}

// ---------------- launch ----------------
extern "C" void kernel_launch(void* const* d_in, const int* in_sizes, int n_in,
                              void* d_out, int out_size) {
    const float* x  = (const float*)d_in[0];
    const float* W1 = (const float*)d_in[1];
    const float* b1 = (const float*)d_in[2];
    const float* W2 = (const float*)d_in[3];
    const float* b2 = (const float*)d_in[4];
    const float* W3 = (const float*)d_in[5];
    const float* b3 = (const float*)d_in[6];
    const float* Wl = (const float*)d_in[7];
    const float* bl = (const float*)d_in[8];
    const void*  ei = d_in[9];
    const void*  bt = d_in[10];

    int N = in_sizes[0] / HDIM;
    int E = in_sizes[9] / 2;
    int G = out_size / CDIM;

    k_detect<<<1, 32>>>(ei);
    k_zero_cnt<<<(N + 255) / 256, 256>>>(N);
    k_deg<<<(E + 255) / 256, 256>>>(ei, E);
    k_dinv<<<(N + 255) / 256, 256>>>(N);

    int nb = (N + 1023) / 1024;
    k_scan1<<<nb, 1024>>>(N);
    k_scan2<<<1, 32>>>(nb, N);
    k_scan3<<<nb, 1024>>>(N);
    k_fill<<<(E + 255) / 256, 256>>>(ei, E);

    int gemm_blocks = (N + BM - 1) / BM;
    int agg_blocks  = (N + 7) / 8;

    k_gemm<<<gemm_blocks, 256>>>(x, W1, N);
    k_agg<<<agg_blocks, 256>>>(b1, N);
    k_gemm<<<gemm_blocks, 256>>>(nullptr, W2, N);
    k_agg<<<agg_blocks, 256>>>(b2, N);
    k_gemm<<<gemm_blocks, 256>>>(nullptr, W3, N);
    k_agg<<<agg_blocks, 256>>>(b3, N);

    k_zero_pool<<<(G * HDIM + 255) / 256, 256>>>(G);
    k_gcount<<<(N + 255) / 256, 256>>>(bt, N);
    k_pool<<<(N + 255) / 256, 128>>>(bt, N);
    k_cls<<<G, 32>>>(Wl, bl, (float*)d_out);
}

// round 5
// speedup vs baseline: 1.7254x; 1.0777x over previous
#include <cuda_runtime.h>
#include <cstdint>

#define HDIM 128
#define MAXN 50000
#define MAXE 600000
#define MAXG 128
#define CDIM 10
#define BM 128
#define BK 16

// ---------------- scratch (no allocations allowed) ----------------
__device__ int   g_is64;
__device__ int   g_cnt[MAXN];
__device__ float g_dinv[MAXN];
__device__ int   g_ptr[MAXN + 1];
__device__ int   g_pos[MAXN];
__device__ int   g_csrc[MAXE];
__device__ int   g_bsum[128];
__device__ float g_h[(size_t)MAXN * HDIM];
__device__ float g_tmp[(size_t)MAXN * HDIM];
__device__ float g_pool[MAXG * HDIM];
__device__ float g_gcnt[MAXG];

__device__ __forceinline__ int loadIdx(const void* p, long long i, int is64) {
    if (is64) return (int)((const long long*)p)[i];
    return ((const int*)p)[i];
}

// ---------------- fused prep: detect dtype + zero counters ----------------
__global__ void k_init(const void* ei, int n, int g) {
    int i = blockIdx.x * blockDim.x + threadIdx.x;
    if (i == 0) {
        const int* w = (const int*)ei;
        int all0 = 1;
        for (int j = 0; j < 32; j++) if (w[2 * j + 1] != 0) all0 = 0;
        g_is64 = all0;
    }
    if (i < n) g_cnt[i] = 0;
    if (i < g * HDIM) g_pool[i] = 0.f;
    if (i < g) g_gcnt[i] = 0.f;
}

__global__ void k_deg(const void* ei, int E) {
    int e = blockIdx.x * blockDim.x + threadIdx.x;
    if (e >= E) return;
    int d = loadIdx(ei, (long long)E + e, g_is64);
    atomicAdd(&g_cnt[d], 1);
}

// scan phase 1 (per-block Hillis-Steele) + dinv
__global__ void k_scan1(int n) {
    __shared__ int s[1024];
    int tid = threadIdx.x;
    int i = blockIdx.x * 1024 + tid;
    int v = (i < n) ? g_cnt[i] : 0;
    if (i < n) g_dinv[i] = rsqrtf((float)(v + 1));   // +1 = self-loop
    s[tid] = v;
    __syncthreads();
    for (int off = 1; off < 1024; off <<= 1) {
        int t = (tid >= off) ? s[tid - off] : 0;
        __syncthreads();
        s[tid] += t;
        __syncthreads();
    }
    if (i < n) g_ptr[i] = s[tid] - v;
    if (tid == 1023) g_bsum[blockIdx.x] = s[tid];
}

// scan phase 2+3 fused: each block computes its carry from g_bsum prefix
__global__ void k_scan23(int n, int nb) {
    __shared__ int carry;
    if (threadIdx.x == 0) {
        int acc = 0;
        for (int b = 0; b < blockIdx.x; b++) acc += g_bsum[b];
        carry = acc;
        if (blockIdx.x == nb - 1) g_ptr[n] = acc + g_bsum[nb - 1];
    }
    __syncthreads();
    int i = blockIdx.x * 1024 + threadIdx.x;
    if (i < n) {
        int p = g_ptr[i] + carry;
        g_ptr[i] = p;
        g_pos[i] = p;
    }
}

__global__ void k_fill(const void* ei, const void* batch, int E, int n) {
    int e = blockIdx.x * blockDim.x + threadIdx.x;
    if (e >= E) return;
    int is64 = g_is64;
    int s = loadIdx(ei, e, is64);
    int d = loadIdx(ei, (long long)E + e, is64);
    int p = atomicAdd(&g_pos[d], 1);
    g_csrc[p] = s;
    if (e < n) {
        int g = loadIdx(batch, e, is64);
        atomicAdd(&g_gcnt[g], 1.0f);
    }
}

// ---------------- f32x2 helpers ----------------
__device__ __forceinline__ uint64_t splat2(float a) {
    uint64_t r;
    asm("mov.b64 %0, {%1, %1};" : "=l"(r) : "f"(a));
    return r;
}
__device__ __forceinline__ void fma2(uint64_t& c, uint64_t a, uint64_t b) {
    asm("fma.rn.f32x2 %0, %1, %2, %0;" : "+l"(c) : "l"(a), "l"(b));
}
__device__ __forceinline__ float2 unpack2(uint64_t v) {
    float2 r;
    asm("mov.b64 {%0, %1}, %2;" : "=f"(r.x), "=f"(r.y) : "l"(v));
    return r;
}

// ---------------- GEMM: g_tmp = A @ W, 8x8 reg tile via packed FFMA2 ----------------
__global__ __launch_bounds__(256, 2) void k_gemm(const float* __restrict__ Aext,
                                                 const float* __restrict__ W,
                                                 int nrows) {
    __shared__ float sA[2][BK][BM];     // A tile transposed: sA[k][row]
    __shared__ float sW[2][BK][HDIM];   // W tile: sW[k][col]
    const float* A = Aext ? Aext : g_h;

    int tid = threadIdx.x;
    int tx = tid & 15;                  // output col group (tx*8 .. +8)
    int ty = tid >> 4;                  // output row group (ty*8 .. +8)
    int rowbase = blockIdx.x * BM;

    int arow = tid >> 2;
    int akg  = tid & 3;
    int wk = tid >> 5;
    int wc = tid & 31;

    float4 aref[2], wref[2];

    // prologue: global -> regs -> smem buf 0
    {
#pragma unroll
        for (int p = 0; p < 2; p++) {
            int r = min(rowbase + arow + p * 64, nrows - 1);
            aref[p] = *(const float4*)&A[(size_t)r * HDIM + akg * 4];
            wref[p] = *(const float4*)&W[(size_t)(wk + p * 8) * HDIM + wc * 4];
        }
#pragma unroll
        for (int p = 0; p < 2; p++) {
            sA[0][akg * 4 + 0][arow + p * 64] = aref[p].x;
            sA[0][akg * 4 + 1][arow + p * 64] = aref[p].y;
            sA[0][akg * 4 + 2][arow + p * 64] = aref[p].z;
            sA[0][akg * 4 + 3][arow + p * 64] = aref[p].w;
            *(float4*)&sW[0][wk + p * 8][wc * 4] = wref[p];
        }
        __syncthreads();
    }

    uint64_t acc[8][4];   // packed f32x2 accumulators: acc[i][j] = (c[i][2j], c[i][2j+1])
#pragma unroll
    for (int i = 0; i < 8; i++)
#pragma unroll
        for (int j = 0; j < 4; j++) acc[i][j] = 0ull;

    const int NT = HDIM / BK;  // 8 k-tiles
#pragma unroll 1
    for (int kt = 0; kt < NT; kt++) {
        int buf = kt & 1;
        if (kt + 1 < NT) {
#pragma unroll
            for (int p = 0; p < 2; p++) {
                int r = min(rowbase + arow + p * 64, nrows - 1);
                aref[p] = *(const float4*)&A[(size_t)r * HDIM + (kt + 1) * BK + akg * 4];
                wref[p] = *(const float4*)&W[(size_t)((kt + 1) * BK + wk + p * 8) * HDIM + wc * 4];
            }
        }

#pragma unroll
        for (int kk = 0; kk < BK; kk++) {
            float4 a0 = *(const float4*)&sA[buf][kk][ty * 8];
            float4 a1 = *(const float4*)&sA[buf][kk][ty * 8 + 4];
            const uint64_t* bp = (const uint64_t*)&sW[buf][kk][tx * 8];
            uint64_t b0 = bp[0], b1 = bp[1], b2 = bp[2], b3 = bp[3];
            uint64_t a2[8];
            a2[0] = splat2(a0.x); a2[1] = splat2(a0.y);
            a2[2] = splat2(a0.z); a2[3] = splat2(a0.w);
            a2[4] = splat2(a1.x); a2[5] = splat2(a1.y);
            a2[6] = splat2(a1.z); a2[7] = splat2(a1.w);
#pragma unroll
            for (int i = 0; i < 8; i++) {
                fma2(acc[i][0], a2[i], b0);
                fma2(acc[i][1], a2[i], b1);
                fma2(acc[i][2], a2[i], b2);
                fma2(acc[i][3], a2[i], b3);
            }
        }

        if (kt + 1 < NT) {
            int nb = buf ^ 1;
#pragma unroll
            for (int p = 0; p < 2; p++) {
                sA[nb][akg * 4 + 0][arow + p * 64] = aref[p].x;
                sA[nb][akg * 4 + 1][arow + p * 64] = aref[p].y;
                sA[nb][akg * 4 + 2][arow + p * 64] = aref[p].z;
                sA[nb][akg * 4 + 3][arow + p * 64] = aref[p].w;
                *(float4*)&sW[nb][wk + p * 8][wc * 4] = wref[p];
            }
            __syncthreads();
        }
    }

    // epilogue
#pragma unroll
    for (int i = 0; i < 8; i++) {
        int r = rowbase + ty * 8 + i;
        if (r < nrows) {
            float2 c0 = unpack2(acc[i][0]);
            float2 c1 = unpack2(acc[i][1]);
            float2 c2 = unpack2(acc[i][2]);
            float2 c3 = unpack2(acc[i][3]);
            float4 o0 = make_float4(c0.x, c0.y, c1.x, c1.y);
            float4 o1 = make_float4(c2.x, c2.y, c3.x, c3.y);
            *(float4*)&g_tmp[(size_t)r * HDIM + tx * 8] = o0;
            *(float4*)&g_tmp[(size_t)r * HDIM + tx * 8 + 4] = o1;
        }
    }
}

// ---------------- aggregation: g_h = relu(D^-1/2 A D^-1/2 * g_tmp + b) ----------------
__global__ __launch_bounds__(256) void k_agg(const float* __restrict__ bias, int n) {
    int warp = threadIdx.x >> 5, lane = threadIdx.x & 31;
    int node = blockIdx.x * 8 + warp;
    if (node >= n) return;
    const float4* t4 = (const float4*)g_tmp;
    float4 acc = make_float4(0.f, 0.f, 0.f, 0.f);
    int beg = g_ptr[node], end = g_ptr[node + 1];
#pragma unroll 4
    for (int p = beg; p < end; p++) {
        int s = g_csrc[p];
        float ds = g_dinv[s];
        float4 v = t4[(size_t)s * 32 + lane];
        acc.x += ds * v.x; acc.y += ds * v.y;
        acc.z += ds * v.z; acc.w += ds * v.w;
    }
    float di = g_dinv[node];
    float di2 = di * di;
    float4 sv = t4[(size_t)node * 32 + lane];
    float4 b = ((const float4*)bias)[lane];
    float4 r;
    r.x = fmaxf(di * acc.x + di2 * sv.x + b.x, 0.f);
    r.y = fmaxf(di * acc.y + di2 * sv.y + b.y, 0.f);
    r.z = fmaxf(di * acc.z + di2 * sv.z + b.z, 0.f);
    r.w = fmaxf(di * acc.w + di2 * sv.w + b.w, 0.f);
    ((float4*)g_h)[(size_t)node * 32 + lane] = r;
}

// ---------------- pooling (batch sorted: run-length accumulate) ----------------
__global__ __launch_bounds__(128) void k_pool(const void* batch, int n) {
    int f = threadIdx.x;
    int n0 = blockIdx.x * 256;
    int n1 = min(n0 + 256, n);
    if (n0 >= n) return;
    int is64 = g_is64;
    int curg = loadIdx(batch, n0, is64);
    float acc = 0.f;
    for (int i = n0; i < n1; i++) {
        int g = loadIdx(batch, i, is64);
        if (g != curg) {
            atomicAdd(&g_pool[curg * HDIM + f], acc);
            acc = 0.f; curg = g;
        }
        acc += g_h[(size_t)i * HDIM + f];
    }
    atomicAdd(&g_pool[curg * HDIM + f], acc);
}

// ---------------- classifier ----------------
__global__ void k_cls(const float* __restrict__ Wl, const float* __restrict__ bl,
                      float* __restrict__ out) {
    int g = blockIdx.x;
    int lane = threadIdx.x;
    float invc = 1.0f / fmaxf(g_gcnt[g], 1.0f);
    float acc = (lane < CDIM) ? bl[lane] : 0.f;
    for (int k = 0; k < HDIM; k++) {
        float p = g_pool[g * HDIM + k] * invc;
        if (lane < CDIM) acc += p * Wl[k * CDIM + lane];
    }
    if (lane < CDIM) out[g * CDIM + lane] = acc;
}

// ---------------- launch ----------------
extern "C" void kernel_launch(void* const* d_in, const int* in_sizes, int n_in,
                              void* d_out, int out_size) {
    const float* x  = (const float*)d_in[0];
    const float* W1 = (const float*)d_in[1];
    const float* b1 = (const float*)d_in[2];
    const float* W2 = (const float*)d_in[3];
    const float* b2 = (const float*)d_in[4];
    const float* W3 = (const float*)d_in[5];
    const float* b3 = (const float*)d_in[6];
    const float* Wl = (const float*)d_in[7];
    const float* bl = (const float*)d_in[8];
    const void*  ei = d_in[9];
    const void*  bt = d_in[10];

    int N = in_sizes[0] / HDIM;
    int E = in_sizes[9] / 2;
    int G = out_size / CDIM;

    int nb = (N + 1023) / 1024;
    int gemm_blocks = (N + BM - 1) / BM;
    int agg_blocks  = (N + 7) / 8;

    k_init<<<(N + 255) / 256, 256>>>(ei, N, G);          // 1
    k_deg<<<(E + 255) / 256, 256>>>(ei, E);              // 2
    k_scan1<<<nb, 1024>>>(N);                            // 3
    k_scan23<<<nb, 1024>>>(N, nb);                       // 4
    k_fill<<<(E + 255) / 256, 256>>>(ei, bt, E, N);      // 5

    k_gemm<<<gemm_blocks, 256>>>(x, W1, N);              // 6 <- profiled
    k_agg<<<agg_blocks, 256>>>(b1, N);
    k_gemm<<<gemm_blocks, 256>>>(nullptr, W2, N);
    k_agg<<<agg_blocks, 256>>>(b2, N);
    k_gemm<<<gemm_blocks, 256>>>(nullptr, W3, N);
    k_agg<<<agg_blocks, 256>>>(b3, N);

    k_pool<<<(N + 255) / 256, 128>>>(bt, N);
    k_cls<<<G, 32>>>(Wl, bl, (float*)d_out);
}

// round 6
// speedup vs baseline: 2.1799x; 1.2634x over previous
#include <cuda_runtime.h>
#include <cstdint>

#define HDIM 128
#define MAXN 50000
#define MAXE 600000
#define MAXG 128
#define CDIM 10
#define BM 128
#define BK 16

// ---------------- scratch (no allocations allowed) ----------------
__device__ int   g_is64;
__device__ int   g_cnt[MAXN];
__device__ float g_dinv[MAXN];
__device__ int   g_ptr[MAXN + 1];
__device__ int   g_pos[MAXN];
__device__ int   g_csrc[MAXE];
__device__ int   g_bsum[128];
__device__ float g_h[(size_t)MAXN * HDIM];
__device__ float g_tmp[(size_t)MAXN * HDIM];
__device__ float g_pool[MAXG * HDIM];
__device__ float g_gcnt[MAXG];

__device__ __forceinline__ int loadIdx(const void* p, long long i, int is64) {
    if (is64) return (int)((const long long*)p)[i];
    return ((const int*)p)[i];
}

// ---------------- fused prep: detect dtype + zero counters ----------------
__global__ void k_init(const void* ei, int n, int g) {
    int i = blockIdx.x * blockDim.x + threadIdx.x;
    if (i == 0) {
        const int* w = (const int*)ei;
        int all0 = 1;
        for (int j = 0; j < 32; j++) if (w[2 * j + 1] != 0) all0 = 0;
        g_is64 = all0;
    }
    if (i < n) g_cnt[i] = 0;
    if (i < g * HDIM) g_pool[i] = 0.f;
    if (i < g) g_gcnt[i] = 0.f;
}

__global__ void k_deg(const void* ei, int E) {
    int e = blockIdx.x * blockDim.x + threadIdx.x;
    if (e >= E) return;
    int d = loadIdx(ei, (long long)E + e, g_is64);
    atomicAdd(&g_cnt[d], 1);
}

// scan phase 1 (per-block Hillis-Steele) + dinv
__global__ void k_scan1(int n) {
    __shared__ int s[1024];
    int tid = threadIdx.x;
    int i = blockIdx.x * 1024 + tid;
    int v = (i < n) ? g_cnt[i] : 0;
    if (i < n) g_dinv[i] = rsqrtf((float)(v + 1));   // +1 = self-loop
    s[tid] = v;
    __syncthreads();
    for (int off = 1; off < 1024; off <<= 1) {
        int t = (tid >= off) ? s[tid - off] : 0;
        __syncthreads();
        s[tid] += t;
        __syncthreads();
    }
    if (i < n) g_ptr[i] = s[tid] - v;
    if (tid == 1023) g_bsum[blockIdx.x] = s[tid];
}

// scan phase 2+3 fused: each block computes its carry from g_bsum prefix
__global__ void k_scan23(int n, int nb) {
    __shared__ int carry;
    if (threadIdx.x == 0) {
        int acc = 0;
        for (int b = 0; b < blockIdx.x; b++) acc += g_bsum[b];
        carry = acc;
        if (blockIdx.x == nb - 1) g_ptr[n] = acc + g_bsum[nb - 1];
    }
    __syncthreads();
    int i = blockIdx.x * 1024 + threadIdx.x;
    if (i < n) {
        int p = g_ptr[i] + carry;
        g_ptr[i] = p;
        g_pos[i] = p;
    }
}

__global__ void k_fill(const void* ei, const void* batch, int E, int n) {
    int e = blockIdx.x * blockDim.x + threadIdx.x;
    if (e >= E) return;
    int is64 = g_is64;
    int s = loadIdx(ei, e, is64);
    int d = loadIdx(ei, (long long)E + e, is64);
    int p = atomicAdd(&g_pos[d], 1);
    g_csrc[p] = s;
    if (e < n) {
        int g = loadIdx(batch, e, is64);
        atomicAdd(&g_gcnt[g], 1.0f);
    }
}

// ---------------- f32x2 helpers ----------------
__device__ __forceinline__ uint64_t splat2(float a) {
    uint64_t r;
    asm("mov.b64 %0, {%1, %1};" : "=l"(r) : "f"(a));
    return r;
}
__device__ __forceinline__ void fma2(uint64_t& c, uint64_t a, uint64_t b) {
    asm("fma.rn.f32x2 %0, %1, %2, %0;" : "+l"(c) : "l"(a), "l"(b));
}
__device__ __forceinline__ float2 unpack2(uint64_t v) {
    float2 r;
    asm("mov.b64 {%0, %1}, %2;" : "=f"(r.x), "=f"(r.y) : "l"(v));
    return r;
}

// ---------------- GEMM: g_tmp = A @ W, 8x8 reg tile via packed FFMA2 ----------------
__global__ __launch_bounds__(256, 2) void k_gemm(const float* __restrict__ Aext,
                                                 const float* __restrict__ W,
                                                 int nrows) {
    __shared__ float sA[2][BK][BM];     // A tile transposed: sA[k][row]
    __shared__ float sW[2][BK][HDIM];   // W tile: sW[k][col]
    const float* A = Aext ? Aext : g_h;

    int tid = threadIdx.x;
    int tx = tid & 15;
    int ty = tid >> 4;
    int rowbase = blockIdx.x * BM;

    int arow = tid >> 2;
    int akg  = tid & 3;
    int wk = tid >> 5;
    int wc = tid & 31;

    float4 aref[2], wref[2];

    {
#pragma unroll
        for (int p = 0; p < 2; p++) {
            int r = min(rowbase + arow + p * 64, nrows - 1);
            aref[p] = *(const float4*)&A[(size_t)r * HDIM + akg * 4];
            wref[p] = *(const float4*)&W[(size_t)(wk + p * 8) * HDIM + wc * 4];
        }
#pragma unroll
        for (int p = 0; p < 2; p++) {
            sA[0][akg * 4 + 0][arow + p * 64] = aref[p].x;
            sA[0][akg * 4 + 1][arow + p * 64] = aref[p].y;
            sA[0][akg * 4 + 2][arow + p * 64] = aref[p].z;
            sA[0][akg * 4 + 3][arow + p * 64] = aref[p].w;
            *(float4*)&sW[0][wk + p * 8][wc * 4] = wref[p];
        }
        __syncthreads();
    }

    uint64_t acc[8][4];
#pragma unroll
    for (int i = 0; i < 8; i++)
#pragma unroll
        for (int j = 0; j < 4; j++) acc[i][j] = 0ull;

    const int NT = HDIM / BK;
#pragma unroll 1
    for (int kt = 0; kt < NT; kt++) {
        int buf = kt & 1;
        if (kt + 1 < NT) {
#pragma unroll
            for (int p = 0; p < 2; p++) {
                int r = min(rowbase + arow + p * 64, nrows - 1);
                aref[p] = *(const float4*)&A[(size_t)r * HDIM + (kt + 1) * BK + akg * 4];
                wref[p] = *(const float4*)&W[(size_t)((kt + 1) * BK + wk + p * 8) * HDIM + wc * 4];
            }
        }

#pragma unroll
        for (int kk = 0; kk < BK; kk++) {
            float4 a0 = *(const float4*)&sA[buf][kk][ty * 8];
            float4 a1 = *(const float4*)&sA[buf][kk][ty * 8 + 4];
            const uint64_t* bp = (const uint64_t*)&sW[buf][kk][tx * 8];
            uint64_t b0 = bp[0], b1 = bp[1], b2 = bp[2], b3 = bp[3];
            uint64_t a2[8];
            a2[0] = splat2(a0.x); a2[1] = splat2(a0.y);
            a2[2] = splat2(a0.z); a2[3] = splat2(a0.w);
            a2[4] = splat2(a1.x); a2[5] = splat2(a1.y);
            a2[6] = splat2(a1.z); a2[7] = splat2(a1.w);
#pragma unroll
            for (int i = 0; i < 8; i++) {
                fma2(acc[i][0], a2[i], b0);
                fma2(acc[i][1], a2[i], b1);
                fma2(acc[i][2], a2[i], b2);
                fma2(acc[i][3], a2[i], b3);
            }
        }

        if (kt + 1 < NT) {
            int nb = buf ^ 1;
#pragma unroll
            for (int p = 0; p < 2; p++) {
                sA[nb][akg * 4 + 0][arow + p * 64] = aref[p].x;
                sA[nb][akg * 4 + 1][arow + p * 64] = aref[p].y;
                sA[nb][akg * 4 + 2][arow + p * 64] = aref[p].z;
                sA[nb][akg * 4 + 3][arow + p * 64] = aref[p].w;
                *(float4*)&sW[nb][wk + p * 8][wc * 4] = wref[p];
            }
            __syncthreads();
        }
    }

#pragma unroll
    for (int i = 0; i < 8; i++) {
        int r = rowbase + ty * 8 + i;
        if (r < nrows) {
            float2 c0 = unpack2(acc[i][0]);
            float2 c1 = unpack2(acc[i][1]);
            float2 c2 = unpack2(acc[i][2]);
            float2 c3 = unpack2(acc[i][3]);
            float4 o0 = make_float4(c0.x, c0.y, c1.x, c1.y);
            float4 o1 = make_float4(c2.x, c2.y, c3.x, c3.y);
            *(float4*)&g_tmp[(size_t)r * HDIM + tx * 8] = o0;
            *(float4*)&g_tmp[(size_t)r * HDIM + tx * 8 + 4] = o1;
        }
    }
}

// ---------------- aggregation: g_h = relu(D^-1/2 A D^-1/2 * g_tmp + b) ----------------
__global__ __launch_bounds__(256) void k_agg(const float* __restrict__ bias, int n) {
    int warp = threadIdx.x >> 5, lane = threadIdx.x & 31;
    int node = blockIdx.x * 8 + warp;
    if (node >= n) return;
    const float4* t4 = (const float4*)g_tmp;
    float4 acc = make_float4(0.f, 0.f, 0.f, 0.f);
    int beg = g_ptr[node], end = g_ptr[node + 1];
#pragma unroll 4
    for (int p = beg; p < end; p++) {
        int s = g_csrc[p];
        float ds = g_dinv[s];
        float4 v = t4[(size_t)s * 32 + lane];
        acc.x += ds * v.x; acc.y += ds * v.y;
        acc.z += ds * v.z; acc.w += ds * v.w;
    }
    float di = g_dinv[node];
    float di2 = di * di;
    float4 sv = t4[(size_t)node * 32 + lane];
    float4 b = ((const float4*)bias)[lane];
    float4 r;
    r.x = fmaxf(di * acc.x + di2 * sv.x + b.x, 0.f);
    r.y = fmaxf(di * acc.y + di2 * sv.y + b.y, 0.f);
    r.z = fmaxf(di * acc.z + di2 * sv.z + b.z, 0.f);
    r.w = fmaxf(di * acc.w + di2 * sv.w + b.w, 0.f);
    ((float4*)g_h)[(size_t)node * 32 + lane] = r;
}

// ---------------- pooling (batch sorted: run-length accumulate, 64-node chunks) ----------------
#define PCHUNK 64
__global__ __launch_bounds__(128) void k_pool(const void* batch, int n) {
    int f = threadIdx.x;
    int n0 = blockIdx.x * PCHUNK;
    int n1 = min(n0 + PCHUNK, n);
    if (n0 >= n) return;
    int is64 = g_is64;
    int curg = loadIdx(batch, n0, is64);
    float acc = 0.f;
    for (int i = n0; i < n1; i++) {
        int g = loadIdx(batch, i, is64);
        if (g != curg) {
            atomicAdd(&g_pool[curg * HDIM + f], acc);
            acc = 0.f; curg = g;
        }
        acc += g_h[(size_t)i * HDIM + f];
    }
    atomicAdd(&g_pool[curg * HDIM + f], acc);
}

// ---------------- classifier ----------------
__global__ void k_cls(const float* __restrict__ Wl, const float* __restrict__ bl,
                      float* __restrict__ out) {
    int g = blockIdx.x;
    int lane = threadIdx.x;
    float invc = 1.0f / fmaxf(g_gcnt[g], 1.0f);
    float acc = (lane < CDIM) ? bl[lane] : 0.f;
    for (int k = 0; k < HDIM; k++) {
        float p = g_pool[g * HDIM + k] * invc;
        if (lane < CDIM) acc += p * Wl[k * CDIM + lane];
    }
    if (lane < CDIM) out[g * CDIM + lane] = acc;
}

// ---------------- launch (fork/join: prep chain overlaps GEMM1) ----------------
extern "C" void kernel_launch(void* const* d_in, const int* in_sizes, int n_in,
                              void* d_out, int out_size) {
    const float* x  = (const float*)d_in[0];
    const float* W1 = (const float*)d_in[1];
    const float* b1 = (const float*)d_in[2];
    const float* W2 = (const float*)d_in[3];
    const float* b2 = (const float*)d_in[4];
    const float* W3 = (const float*)d_in[5];
    const float* b3 = (const float*)d_in[6];
    const float* Wl = (const float*)d_in[7];
    const float* bl = (const float*)d_in[8];
    const void*  ei = d_in[9];
    const void*  bt = d_in[10];

    int N = in_sizes[0] / HDIM;
    int E = in_sizes[9] / 2;
    int G = out_size / CDIM;

    // side stream + events, created on first (uncaptured) call
    static cudaStream_t s_side = nullptr;
    static cudaEvent_t ev_fork = nullptr, ev_join = nullptr;
    if (!s_side) {
        cudaStreamCreateWithFlags(&s_side, cudaStreamNonBlocking);
        cudaEventCreateWithFlags(&ev_fork, cudaEventDisableTiming);
        cudaEventCreateWithFlags(&ev_join, cudaEventDisableTiming);
    }

    int nb = (N + 1023) / 1024;
    int gemm_blocks = (N + BM - 1) / BM;
    int agg_blocks  = (N + 7) / 8;

    // fork: prep chain on side stream, GEMM1 on main (independent of prep)
    cudaEventRecord(ev_fork, 0);
    cudaStreamWaitEvent(s_side, ev_fork, 0);

    k_init<<<(N + 255) / 256, 256, 0, s_side>>>(ei, N, G);
    k_deg<<<(E + 255) / 256, 256, 0, s_side>>>(ei, E);
    k_scan1<<<nb, 1024, 0, s_side>>>(N);
    k_scan23<<<nb, 1024, 0, s_side>>>(N, nb);
    k_fill<<<(E + 255) / 256, 256, 0, s_side>>>(ei, bt, E, N);
    cudaEventRecord(ev_join, s_side);

    k_gemm<<<gemm_blocks, 256>>>(x, W1, N);

    // join: agg needs both CSR (side) and g_tmp (main)
    cudaStreamWaitEvent(0, ev_join, 0);

    k_agg<<<agg_blocks, 256>>>(b1, N);
    k_gemm<<<gemm_blocks, 256>>>(nullptr, W2, N);
    k_agg<<<agg_blocks, 256>>>(b2, N);
    k_gemm<<<gemm_blocks, 256>>>(nullptr, W3, N);
    k_agg<<<agg_blocks, 256>>>(b3, N);

    k_pool<<<(N + PCHUNK - 1) / PCHUNK, 128>>>(bt, N);
    k_cls<<<G, 32>>>(Wl, bl, (float*)d_out);
}

// round 7
// speedup vs baseline: 2.3728x; 1.0885x over previous
#include <cuda_runtime.h>
#include <cuda_fp16.h>
#include <cstdint>

#define HDIM 128
#define MAXN 50000
#define MAXE 600000
#define MAXG 128
#define CDIM 10
#define BM 128
#define BK 16

// ---------------- scratch (no allocations allowed) ----------------
__device__ int    g_is64;
__device__ int    g_cnt[MAXN];
__device__ float  g_dinv[MAXN];
__device__ int    g_ptr[MAXN + 1];
__device__ int    g_pos[MAXN];
__device__ int    g_csrc[MAXE];
__device__ int    g_bsum[128];
__device__ float  g_h[(size_t)MAXN * HDIM];
__device__ __half g_tmp[(size_t)MAXN * HDIM];   // fp16: halves agg gather traffic
__device__ float  g_pool[MAXG * HDIM];
__device__ float  g_gcnt[MAXG];

__device__ __forceinline__ int loadIdx(const void* p, long long i, int is64) {
    if (is64) return (int)((const long long*)p)[i];
    return ((const int*)p)[i];
}

// ---------------- fused prep: detect dtype + zero counters ----------------
__global__ void k_init(const void* ei, int n, int g) {
    int i = blockIdx.x * blockDim.x + threadIdx.x;
    if (i == 0) {
        const int* w = (const int*)ei;
        int all0 = 1;
        for (int j = 0; j < 32; j++) if (w[2 * j + 1] != 0) all0 = 0;
        g_is64 = all0;
    }
    if (i < n) g_cnt[i] = 0;
    if (i < g * HDIM) g_pool[i] = 0.f;
    if (i < g) g_gcnt[i] = 0.f;
}

__global__ void k_deg(const void* ei, int E) {
    int e = blockIdx.x * blockDim.x + threadIdx.x;
    if (e >= E) return;
    int d = loadIdx(ei, (long long)E + e, g_is64);
    atomicAdd(&g_cnt[d], 1);
}

// scan phase 1 (per-block Hillis-Steele) + dinv
__global__ void k_scan1(int n) {
    __shared__ int s[1024];
    int tid = threadIdx.x;
    int i = blockIdx.x * 1024 + tid;
    int v = (i < n) ? g_cnt[i] : 0;
    if (i < n) g_dinv[i] = rsqrtf((float)(v + 1));   // +1 = self-loop
    s[tid] = v;
    __syncthreads();
    for (int off = 1; off < 1024; off <<= 1) {
        int t = (tid >= off) ? s[tid - off] : 0;
        __syncthreads();
        s[tid] += t;
        __syncthreads();
    }
    if (i < n) g_ptr[i] = s[tid] - v;
    if (tid == 1023) g_bsum[blockIdx.x] = s[tid];
}

// scan phase 2+3 fused
__global__ void k_scan23(int n, int nb) {
    __shared__ int carry;
    if (threadIdx.x == 0) {
        int acc = 0;
        for (int b = 0; b < blockIdx.x; b++) acc += g_bsum[b];
        carry = acc;
        if (blockIdx.x == nb - 1) g_ptr[n] = acc + g_bsum[nb - 1];
    }
    __syncthreads();
    int i = blockIdx.x * 1024 + threadIdx.x;
    if (i < n) {
        int p = g_ptr[i] + carry;
        g_ptr[i] = p;
        g_pos[i] = p;
    }
}

__global__ void k_fill(const void* ei, const void* batch, int E, int n) {
    int e = blockIdx.x * blockDim.x + threadIdx.x;
    if (e >= E) return;
    int is64 = g_is64;
    int s = loadIdx(ei, e, is64);
    int d = loadIdx(ei, (long long)E + e, is64);
    int p = atomicAdd(&g_pos[d], 1);
    g_csrc[p] = s;
    if (e < n) {
        int g = loadIdx(batch, e, is64);
        atomicAdd(&g_gcnt[g], 1.0f);
    }
}

// ---------------- f32x2 helpers ----------------
__device__ __forceinline__ uint64_t splat2(float a) {
    uint64_t r;
    asm("mov.b64 %0, {%1, %1};" : "=l"(r) : "f"(a));
    return r;
}
__device__ __forceinline__ void fma2(uint64_t& c, uint64_t a, uint64_t b) {
    asm("fma.rn.f32x2 %0, %1, %2, %0;" : "+l"(c) : "l"(a), "l"(b));
}
__device__ __forceinline__ float2 unpack2(uint64_t v) {
    float2 r;
    asm("mov.b64 {%0, %1}, %2;" : "=f"(r.x), "=f"(r.y) : "l"(v));
    return r;
}

// ---------------- GEMM: g_tmp(fp16) = A @ W, 8x8 reg tile via packed FFMA2 ----------------
__global__ __launch_bounds__(256, 2) void k_gemm(const float* __restrict__ Aext,
                                                 const float* __restrict__ W,
                                                 int nrows) {
    __shared__ float sA[2][BK][BM];
    __shared__ float sW[2][BK][HDIM];
    const float* A = Aext ? Aext : g_h;

    int tid = threadIdx.x;
    int tx = tid & 15;
    int ty = tid >> 4;
    int rowbase = blockIdx.x * BM;

    int arow = tid >> 2;
    int akg  = tid & 3;
    int wk = tid >> 5;
    int wc = tid & 31;

    float4 aref[2], wref[2];

    {
#pragma unroll
        for (int p = 0; p < 2; p++) {
            int r = min(rowbase + arow + p * 64, nrows - 1);
            aref[p] = *(const float4*)&A[(size_t)r * HDIM + akg * 4];
            wref[p] = *(const float4*)&W[(size_t)(wk + p * 8) * HDIM + wc * 4];
        }
#pragma unroll
        for (int p = 0; p < 2; p++) {
            sA[0][akg * 4 + 0][arow + p * 64] = aref[p].x;
            sA[0][akg * 4 + 1][arow + p * 64] = aref[p].y;
            sA[0][akg * 4 + 2][arow + p * 64] = aref[p].z;
            sA[0][akg * 4 + 3][arow + p * 64] = aref[p].w;
            *(float4*)&sW[0][wk + p * 8][wc * 4] = wref[p];
        }
        __syncthreads();
    }

    uint64_t acc[8][4];
#pragma unroll
    for (int i = 0; i < 8; i++)
#pragma unroll
        for (int j = 0; j < 4; j++) acc[i][j] = 0ull;

    const int NT = HDIM / BK;
#pragma unroll 1
    for (int kt = 0; kt < NT; kt++) {
        int buf = kt & 1;
        if (kt + 1 < NT) {
#pragma unroll
            for (int p = 0; p < 2; p++) {
                int r = min(rowbase + arow + p * 64, nrows - 1);
                aref[p] = *(const float4*)&A[(size_t)r * HDIM + (kt + 1) * BK + akg * 4];
                wref[p] = *(const float4*)&W[(size_t)((kt + 1) * BK + wk + p * 8) * HDIM + wc * 4];
            }
        }

#pragma unroll
        for (int kk = 0; kk < BK; kk++) {
            float4 a0 = *(const float4*)&sA[buf][kk][ty * 8];
            float4 a1 = *(const float4*)&sA[buf][kk][ty * 8 + 4];
            const uint64_t* bp = (const uint64_t*)&sW[buf][kk][tx * 8];
            uint64_t b0 = bp[0], b1 = bp[1], b2 = bp[2], b3 = bp[3];
            uint64_t a2[8];
            a2[0] = splat2(a0.x); a2[1] = splat2(a0.y);
            a2[2] = splat2(a0.z); a2[3] = splat2(a0.w);
            a2[4] = splat2(a1.x); a2[5] = splat2(a1.y);
            a2[6] = splat2(a1.z); a2[7] = splat2(a1.w);
#pragma unroll
            for (int i = 0; i < 8; i++) {
                fma2(acc[i][0], a2[i], b0);
                fma2(acc[i][1], a2[i], b1);
                fma2(acc[i][2], a2[i], b2);
                fma2(acc[i][3], a2[i], b3);
            }
        }

        if (kt + 1 < NT) {
            int nb = buf ^ 1;
#pragma unroll
            for (int p = 0; p < 2; p++) {
                sA[nb][akg * 4 + 0][arow + p * 64] = aref[p].x;
                sA[nb][akg * 4 + 1][arow + p * 64] = aref[p].y;
                sA[nb][akg * 4 + 2][arow + p * 64] = aref[p].z;
                sA[nb][akg * 4 + 3][arow + p * 64] = aref[p].w;
                *(float4*)&sW[nb][wk + p * 8][wc * 4] = wref[p];
            }
            __syncthreads();
        }
    }

    // epilogue: convert to fp16, 16B store per thread row
#pragma unroll
    for (int i = 0; i < 8; i++) {
        int r = rowbase + ty * 8 + i;
        if (r < nrows) {
            float2 c0 = unpack2(acc[i][0]);
            float2 c1 = unpack2(acc[i][1]);
            float2 c2 = unpack2(acc[i][2]);
            float2 c3 = unpack2(acc[i][3]);
            __half2 h0 = __floats2half2_rn(c0.x, c0.y);
            __half2 h1 = __floats2half2_rn(c1.x, c1.y);
            __half2 h2 = __floats2half2_rn(c2.x, c2.y);
            __half2 h3 = __floats2half2_rn(c3.x, c3.y);
            uint4 o;
            o.x = *(uint32_t*)&h0; o.y = *(uint32_t*)&h1;
            o.z = *(uint32_t*)&h2; o.w = *(uint32_t*)&h3;
            *(uint4*)&g_tmp[(size_t)r * HDIM + tx * 8] = o;
        }
    }
}

// ---------------- aggregation: g_h = relu(D^-1/2 A D^-1/2 * g_tmp + b), fp16 gather ----------------
__global__ __launch_bounds__(256) void k_agg(const float* __restrict__ bias, int n) {
    int warp = threadIdx.x >> 5, lane = threadIdx.x & 31;
    int node = blockIdx.x * 8 + warp;
    if (node >= n) return;
    // lane handles features [lane*4, lane*4+4): 8 bytes = uint2 of 2 half2
    float4 acc = make_float4(0.f, 0.f, 0.f, 0.f);
    int beg = g_ptr[node], end = g_ptr[node + 1];
#pragma unroll 4
    for (int p = beg; p < end; p++) {
        int s = g_csrc[p];
        float ds = g_dinv[s];
        uint2 raw = *(const uint2*)&g_tmp[(size_t)s * HDIM + lane * 4];
        float2 v0 = __half22float2(*(__half2*)&raw.x);
        float2 v1 = __half22float2(*(__half2*)&raw.y);
        acc.x += ds * v0.x; acc.y += ds * v0.y;
        acc.z += ds * v1.x; acc.w += ds * v1.y;
    }
    float di = g_dinv[node];
    float di2 = di * di;
    uint2 sraw = *(const uint2*)&g_tmp[(size_t)node * HDIM + lane * 4];
    float2 s0 = __half22float2(*(__half2*)&sraw.x);
    float2 s1 = __half22float2(*(__half2*)&sraw.y);
    float4 b = ((const float4*)bias)[lane];
    float4 r;
    r.x = fmaxf(di * acc.x + di2 * s0.x + b.x, 0.f);
    r.y = fmaxf(di * acc.y + di2 * s0.y + b.y, 0.f);
    r.z = fmaxf(di * acc.z + di2 * s1.x + b.z, 0.f);
    r.w = fmaxf(di * acc.w + di2 * s1.y + b.w, 0.f);
    ((float4*)g_h)[(size_t)node * 32 + lane] = r;
}

// ---------------- pooling (batch sorted: run-length accumulate, 64-node chunks) ----------------
#define PCHUNK 64
__global__ __launch_bounds__(128) void k_pool(const void* batch, int n) {
    int f = threadIdx.x;
    int n0 = blockIdx.x * PCHUNK;
    int n1 = min(n0 + PCHUNK, n);
    if (n0 >= n) return;
    int is64 = g_is64;
    int curg = loadIdx(batch, n0, is64);
    float acc = 0.f;
    for (int i = n0; i < n1; i++) {
        int g = loadIdx(batch, i, is64);
        if (g != curg) {
            atomicAdd(&g_pool[curg * HDIM + f], acc);
            acc = 0.f; curg = g;
        }
        acc += g_h[(size_t)i * HDIM + f];
    }
    atomicAdd(&g_pool[curg * HDIM + f], acc);
}

// ---------------- classifier ----------------
__global__ void k_cls(const float* __restrict__ Wl, const float* __restrict__ bl,
                      float* __restrict__ out) {
    int g = blockIdx.x;
    int lane = threadIdx.x;
    float invc = 1.0f / fmaxf(g_gcnt[g], 1.0f);
    float acc = (lane < CDIM) ? bl[lane] : 0.f;
    for (int k = 0; k < HDIM; k++) {
        float p = g_pool[g * HDIM + k] * invc;
        if (lane < CDIM) acc += p * Wl[k * CDIM + lane];
    }
    if (lane < CDIM) out[g * CDIM + lane] = acc;
}

// ---------------- launch (fork/join: prep chain overlaps GEMM1) ----------------
extern "C" void kernel_launch(void* const* d_in, const int* in_sizes, int n_in,
                              void* d_out, int out_size) {
    const float* x  = (const float*)d_in[0];
    const float* W1 = (const float*)d_in[1];
    const float* b1 = (const float*)d_in[2];
    const float* W2 = (const float*)d_in[3];
    const float* b2 = (const float*)d_in[4];
    const float* W3 = (const float*)d_in[5];
    const float* b3 = (const float*)d_in[6];
    const float* Wl = (const float*)d_in[7];
    const float* bl = (const float*)d_in[8];
    const void*  ei = d_in[9];
    const void*  bt = d_in[10];

    int N = in_sizes[0] / HDIM;
    int E = in_sizes[9] / 2;
    int G = out_size / CDIM;

    static cudaStream_t s_side = nullptr;
    static cudaEvent_t ev_fork = nullptr, ev_join = nullptr;
    if (!s_side) {
        cudaStreamCreateWithFlags(&s_side, cudaStreamNonBlocking);
        cudaEventCreateWithFlags(&ev_fork, cudaEventDisableTiming);
        cudaEventCreateWithFlags(&ev_join, cudaEventDisableTiming);
    }

    int nb = (N + 1023) / 1024;
    int gemm_blocks = (N + BM - 1) / BM;
    int agg_blocks  = (N + 7) / 8;

    cudaEventRecord(ev_fork, 0);
    cudaStreamWaitEvent(s_side, ev_fork, 0);

    k_init<<<(N + 255) / 256, 256, 0, s_side>>>(ei, N, G);
    k_deg<<<(E + 255) / 256, 256, 0, s_side>>>(ei, E);
    k_scan1<<<nb, 1024, 0, s_side>>>(N);
    k_scan23<<<nb, 1024, 0, s_side>>>(N, nb);
    k_fill<<<(E + 255) / 256, 256, 0, s_side>>>(ei, bt, E, N);
    cudaEventRecord(ev_join, s_side);

    k_gemm<<<gemm_blocks, 256>>>(x, W1, N);

    cudaStreamWaitEvent(0, ev_join, 0);

    k_agg<<<agg_blocks, 256>>>(b1, N);
    k_gemm<<<gemm_blocks, 256>>>(nullptr, W2, N);
    k_agg<<<agg_blocks, 256>>>(b2, N);
    k_gemm<<<gemm_blocks, 256>>>(nullptr, W3, N);
    k_agg<<<agg_blocks, 256>>>(b3, N);

    k_pool<<<(N + PCHUNK - 1) / PCHUNK, 128>>>(bt, N);
    k_cls<<<G, 32>>>(Wl, bl, (float*)d_out);
}

// round 8
// speedup vs baseline: 2.9192x; 1.2303x over previous
#include <cuda_runtime.h>
#include <cuda_fp16.h>
#include <cuda_bf16.h>
#include <cstdint>

#define HDIM 128
#define MAXN 50000
#define MAXE 600000
#define MAXG 128
#define CDIM 10

// ---------------- scratch (no allocations allowed) ----------------
__device__ int      g_is64;
__device__ int      g_cnt[MAXN];
__device__ float    g_dinv[MAXN];
__device__ int      g_ptr[MAXN + 1];
__device__ int      g_pos[MAXN];
__device__ int      g_csrc[MAXE];
__device__ int      g_bsum[128];
__device__ float    g_h[(size_t)MAXN * HDIM];
__device__ __half   g_tmp[(size_t)MAXN * HDIM];
__device__ float    g_pool[MAXG * HDIM];
__device__ float    g_gcnt[MAXG];
__device__ uint32_t g_wth[3][HDIM * 64];   // W^T bf16-hi, packed k-pairs: [n][kp]
__device__ uint32_t g_wtl[3][HDIM * 64];   // W^T bf16-lo

__device__ __forceinline__ int loadIdx(const void* p, long long i, int is64) {
    if (is64) return (int)((const long long*)p)[i];
    return ((const int*)p)[i];
}

// ---------------- fused prep ----------------
__global__ void k_init(const void* ei, int n, int g) {
    int i = blockIdx.x * blockDim.x + threadIdx.x;
    if (i == 0) {
        const int* w = (const int*)ei;
        int all0 = 1;
        for (int j = 0; j < 32; j++) if (w[2 * j + 1] != 0) all0 = 0;
        g_is64 = all0;
    }
    if (i < n) g_cnt[i] = 0;
    if (i < g * HDIM) g_pool[i] = 0.f;
    if (i < g) g_gcnt[i] = 0.f;
}

__global__ void k_deg(const void* ei, int E) {
    int e = blockIdx.x * blockDim.x + threadIdx.x;
    if (e >= E) return;
    int d = loadIdx(ei, (long long)E + e, g_is64);
    atomicAdd(&g_cnt[d], 1);
}

__global__ void k_scan1(int n) {
    __shared__ int s[1024];
    int tid = threadIdx.x;
    int i = blockIdx.x * 1024 + tid;
    int v = (i < n) ? g_cnt[i] : 0;
    if (i < n) g_dinv[i] = rsqrtf((float)(v + 1));   // +1 = self-loop
    s[tid] = v;
    __syncthreads();
    for (int off = 1; off < 1024; off <<= 1) {
        int t = (tid >= off) ? s[tid - off] : 0;
        __syncthreads();
        s[tid] += t;
        __syncthreads();
    }
    if (i < n) g_ptr[i] = s[tid] - v;
    if (tid == 1023) g_bsum[blockIdx.x] = s[tid];
}

__global__ void k_scan23(int n, int nb) {
    __shared__ int carry;
    if (threadIdx.x == 0) {
        int acc = 0;
        for (int b = 0; b < blockIdx.x; b++) acc += g_bsum[b];
        carry = acc;
        if (blockIdx.x == nb - 1) g_ptr[n] = acc + g_bsum[nb - 1];
    }
    __syncthreads();
    int i = blockIdx.x * 1024 + threadIdx.x;
    if (i < n) {
        int p = g_ptr[i] + carry;
        g_ptr[i] = p;
        g_pos[i] = p;
    }
}

__global__ void k_fill(const void* ei, const void* batch, int E, int n) {
    int e = blockIdx.x * blockDim.x + threadIdx.x;
    if (e >= E) return;
    int is64 = g_is64;
    int s = loadIdx(ei, e, is64);
    int d = loadIdx(ei, (long long)E + e, is64);
    int p = atomicAdd(&g_pos[d], 1);
    g_csrc[p] = s;
    if (e < n) {
        int g = loadIdx(batch, e, is64);
        atomicAdd(&g_gcnt[g], 1.0f);
    }
}

// ---------------- W split/transpose: g_wt*[l][n][kp] from W[k][n] ----------------
__global__ void k_wsplit(const float* __restrict__ W1, const float* __restrict__ W2,
                         const float* __restrict__ W3) {
    int i = blockIdx.x * blockDim.x + threadIdx.x;
    if (i >= 3 * HDIM * 64) return;
    int l = i >> 13, r = i & 8191;
    int n = r >> 6, kp = r & 63;
    const float* W = (l == 0) ? W1 : ((l == 1) ? W2 : W3);
    float a = W[(2 * kp) * HDIM + n];
    float b = W[(2 * kp + 1) * HDIM + n];
    float ah = __bfloat162float(__float2bfloat16_rn(a));
    float bh = __bfloat162float(__float2bfloat16_rn(b));
    __nv_bfloat162 hp = __floats2bfloat162_rn(a, b);       // .x = a (low bits)
    __nv_bfloat162 lp = __floats2bfloat162_rn(a - ah, b - bh);
    g_wth[l][n * 64 + kp] = *(uint32_t*)&hp;
    g_wtl[l][n * 64 + kp] = *(uint32_t*)&lp;
}

// ---------------- HMMA helper ----------------
__device__ __forceinline__ void mma_bf16(float* c, const uint32_t* a, uint32_t b0, uint32_t b1) {
    asm volatile("mma.sync.aligned.m16n8k16.row.col.f32.bf16.bf16.f32 "
                 "{%0,%1,%2,%3}, {%4,%5,%6,%7}, {%8,%9}, {%0,%1,%2,%3};"
                 : "+f"(c[0]), "+f"(c[1]), "+f"(c[2]), "+f"(c[3])
                 : "r"(a[0]), "r"(a[1]), "r"(a[2]), "r"(a[3]), "r"(b0), "r"(b1));
}

// ---------------- GEMM: g_tmp(fp16) = A @ W via bf16-split mma.sync ----------------
// smem layout (u32 units), stride 68 per row for conflict-free frag loads
#define SROW 68
#define SA_HI 0
#define SA_LO (SROW * 128)
#define SB_HI (2 * SROW * 128)
#define SB_LO (3 * SROW * 128)
#define GSMEM_BYTES (4 * SROW * 128 * 4)

__global__ __launch_bounds__(256, 1) void k_gemm(const float* __restrict__ Aext,
                                                 int layer, int nrows) {
    extern __shared__ uint32_t sm[];
    const float* A = Aext ? Aext : g_h;
    int tid = threadIdx.x;
    int rowbase = blockIdx.x * 128;

    // load + split A, copy pre-split B
    const uint32_t* wth = g_wth[layer];
    const uint32_t* wtl = g_wtl[layer];
#pragma unroll
    for (int it = 0; it < 32; it++) {
        int idx = tid + it * 256;          // 0..8191
        int row = idx >> 6, kp = idx & 63;
        int r = min(rowbase + row, nrows - 1);
        float2 v = *(const float2*)&A[(size_t)r * HDIM + kp * 2];
        float xh = __bfloat162float(__float2bfloat16_rn(v.x));
        float yh = __bfloat162float(__float2bfloat16_rn(v.y));
        __nv_bfloat162 hp = __floats2bfloat162_rn(v.x, v.y);
        __nv_bfloat162 lp = __floats2bfloat162_rn(v.x - xh, v.y - yh);
        sm[SA_HI + row * SROW + kp] = *(uint32_t*)&hp;
        sm[SA_LO + row * SROW + kp] = *(uint32_t*)&lp;
        sm[SB_HI + row * SROW + kp] = wth[idx];
        sm[SB_LO + row * SROW + kp] = wtl[idx];
    }
    __syncthreads();

    int lane = tid & 31, warp = tid >> 5;
    int g = lane >> 2, tig = lane & 3;
    int wm = warp >> 1, wn = warp & 1;     // 4 m-groups x 2 n-groups
    int m0 = wm * 32, n0 = wn * 64;

    float acc[2][8][4];
#pragma unroll
    for (int i = 0; i < 2; i++)
#pragma unroll
        for (int j = 0; j < 8; j++)
#pragma unroll
            for (int q = 0; q < 4; q++) acc[i][j][q] = 0.f;

#pragma unroll 1
    for (int s = 0; s < 8; s++) {
        int kb = s * 8;
        uint32_t ah[2][4], al[2][4];
#pragma unroll
        for (int i = 0; i < 2; i++) {
            int rb = m0 + i * 16;
            int o0 = (rb + g) * SROW + kb + tig;
            int o1 = (rb + 8 + g) * SROW + kb + tig;
            ah[i][0] = sm[SA_HI + o0];
            ah[i][1] = sm[SA_HI + o1];
            ah[i][2] = sm[SA_HI + o0 + 4];
            ah[i][3] = sm[SA_HI + o1 + 4];
            al[i][0] = sm[SA_LO + o0];
            al[i][1] = sm[SA_LO + o1];
            al[i][2] = sm[SA_LO + o0 + 4];
            al[i][3] = sm[SA_LO + o1 + 4];
        }
#pragma unroll
        for (int j = 0; j < 8; j++) {
            int nn = n0 + j * 8 + g;
            int ob = nn * SROW + kb + tig;
            uint32_t bh0 = sm[SB_HI + ob], bh1 = sm[SB_HI + ob + 4];
            uint32_t bl0 = sm[SB_LO + ob], bl1 = sm[SB_LO + ob + 4];
#pragma unroll
            for (int i = 0; i < 2; i++) {
                mma_bf16(acc[i][j], ah[i], bh0, bh1);
                mma_bf16(acc[i][j], ah[i], bl0, bl1);
                mma_bf16(acc[i][j], al[i], bh0, bh1);
            }
        }
    }

    // epilogue: fp16 g_tmp
#pragma unroll
    for (int i = 0; i < 2; i++) {
#pragma unroll
        for (int j = 0; j < 8; j++) {
            int r0 = rowbase + m0 + i * 16 + g;
            int c = n0 + j * 8 + tig * 2;
            if (r0 < nrows) {
                __half2 h = __floats2half2_rn(acc[i][j][0], acc[i][j][1]);
                *(__half2*)&g_tmp[(size_t)r0 * HDIM + c] = h;
            }
            int r1 = r0 + 8;
            if (r1 < nrows) {
                __half2 h = __floats2half2_rn(acc[i][j][2], acc[i][j][3]);
                *(__half2*)&g_tmp[(size_t)r1 * HDIM + c] = h;
            }
        }
    }
}

// ---------------- aggregation: g_h = relu(D^-1/2 A D^-1/2 * g_tmp + b) ----------------
__global__ __launch_bounds__(256) void k_agg(const float* __restrict__ bias, int n) {
    int warp = threadIdx.x >> 5, lane = threadIdx.x & 31;
    int node = blockIdx.x * 8 + warp;
    if (node >= n) return;
    float4 acc = make_float4(0.f, 0.f, 0.f, 0.f);
    int beg = g_ptr[node], end = g_ptr[node + 1];
#pragma unroll 4
    for (int p = beg; p < end; p++) {
        int s = g_csrc[p];
        float ds = g_dinv[s];
        uint2 raw = *(const uint2*)&g_tmp[(size_t)s * HDIM + lane * 4];
        float2 v0 = __half22float2(*(__half2*)&raw.x);
        float2 v1 = __half22float2(*(__half2*)&raw.y);
        acc.x += ds * v0.x; acc.y += ds * v0.y;
        acc.z += ds * v1.x; acc.w += ds * v1.y;
    }
    float di = g_dinv[node];
    float di2 = di * di;
    uint2 sraw = *(const uint2*)&g_tmp[(size_t)node * HDIM + lane * 4];
    float2 s0 = __half22float2(*(__half2*)&sraw.x);
    float2 s1 = __half22float2(*(__half2*)&sraw.y);
    float4 b = ((const float4*)bias)[lane];
    float4 r;
    r.x = fmaxf(di * acc.x + di2 * s0.x + b.x, 0.f);
    r.y = fmaxf(di * acc.y + di2 * s0.y + b.y, 0.f);
    r.z = fmaxf(di * acc.z + di2 * s1.x + b.z, 0.f);
    r.w = fmaxf(di * acc.w + di2 * s1.y + b.w, 0.f);
    ((float4*)g_h)[(size_t)node * 32 + lane] = r;
}

// ---------------- pooling ----------------
#define PCHUNK 64
__global__ __launch_bounds__(128) void k_pool(const void* batch, int n) {
    int f = threadIdx.x;
    int n0 = blockIdx.x * PCHUNK;
    int n1 = min(n0 + PCHUNK, n);
    if (n0 >= n) return;
    int is64 = g_is64;
    int curg = loadIdx(batch, n0, is64);
    float acc = 0.f;
    for (int i = n0; i < n1; i++) {
        int g = loadIdx(batch, i, is64);
        if (g != curg) {
            atomicAdd(&g_pool[curg * HDIM + f], acc);
            acc = 0.f; curg = g;
        }
        acc += g_h[(size_t)i * HDIM + f];
    }
    atomicAdd(&g_pool[curg * HDIM + f], acc);
}

// ---------------- classifier ----------------
__global__ void k_cls(const float* __restrict__ Wl, const float* __restrict__ bl,
                      float* __restrict__ out) {
    int g = blockIdx.x;
    int lane = threadIdx.x;
    float invc = 1.0f / fmaxf(g_gcnt[g], 1.0f);
    float acc = (lane < CDIM) ? bl[lane] : 0.f;
    for (int k = 0; k < HDIM; k++) {
        float p = g_pool[g * HDIM + k] * invc;
        if (lane < CDIM) acc += p * Wl[k * CDIM + lane];
    }
    if (lane < CDIM) out[g * CDIM + lane] = acc;
}

// ---------------- launch ----------------
extern "C" void kernel_launch(void* const* d_in, const int* in_sizes, int n_in,
                              void* d_out, int out_size) {
    const float* x  = (const float*)d_in[0];
    const float* W1 = (const float*)d_in[1];
    const float* b1 = (const float*)d_in[2];
    const float* W2 = (const float*)d_in[3];
    const float* b2 = (const float*)d_in[4];
    const float* W3 = (const float*)d_in[5];
    const float* b3 = (const float*)d_in[6];
    const float* Wl = (const float*)d_in[7];
    const float* bl = (const float*)d_in[8];
    const void*  ei = d_in[9];
    const void*  bt = d_in[10];

    int N = in_sizes[0] / HDIM;
    int E = in_sizes[9] / 2;
    int G = out_size / CDIM;

    static cudaStream_t s_side = nullptr;
    static cudaEvent_t ev_fork = nullptr, ev_join = nullptr;
    if (!s_side) {
        cudaStreamCreateWithFlags(&s_side, cudaStreamNonBlocking);
        cudaEventCreateWithFlags(&ev_fork, cudaEventDisableTiming);
        cudaEventCreateWithFlags(&ev_join, cudaEventDisableTiming);
        cudaFuncSetAttribute(k_gemm, cudaFuncAttributeMaxDynamicSharedMemorySize, GSMEM_BYTES);
    }

    int nb = (N + 1023) / 1024;
    int gemm_blocks = (N + 127) / 128;
    int agg_blocks  = (N + 7) / 8;

    // fork: CSR prep on side stream; W split + GEMM1 on main
    cudaEventRecord(ev_fork, 0);
    cudaStreamWaitEvent(s_side, ev_fork, 0);

    k_init<<<(N + 255) / 256, 256, 0, s_side>>>(ei, N, G);
    k_deg<<<(E + 255) / 256, 256, 0, s_side>>>(ei, E);
    k_scan1<<<nb, 1024, 0, s_side>>>(N);
    k_scan23<<<nb, 1024, 0, s_side>>>(N, nb);
    k_fill<<<(E + 255) / 256, 256, 0, s_side>>>(ei, bt, E, N);
    cudaEventRecord(ev_join, s_side);

    k_wsplit<<<(3 * HDIM * 64 + 255) / 256, 256>>>(W1, W2, W3);
    k_gemm<<<gemm_blocks, 256, GSMEM_BYTES>>>(x, 0, N);

    cudaStreamWaitEvent(0, ev_join, 0);

    k_agg<<<agg_blocks, 256>>>(b1, N);
    k_gemm<<<gemm_blocks, 256, GSMEM_BYTES>>>(nullptr, 1, N);
    k_agg<<<agg_blocks, 256>>>(b2, N);
    k_gemm<<<gemm_blocks, 256, GSMEM_BYTES>>>(nullptr, 2, N);
    k_agg<<<agg_blocks, 256>>>(b3, N);

    k_pool<<<(N + PCHUNK - 1) / PCHUNK, 128>>>(bt, N);
    k_cls<<<G, 32>>>(Wl, bl, (float*)d_out);
}